// round 3
// baseline (speedup 1.0000x reference)
#include <cuda_runtime.h>

// out[i*2+0] = sum of edge_attr[e] for edges with edgeij_pair[0][e] == i
// out[i*2+1] = vertex_attr[i*2+1]

__device__ __forceinline__ void red_add_f32(float* addr, float v) {
    asm volatile("red.global.add.f32 [%0], %1;" :: "l"(addr), "f"(v) : "memory");
}

__global__ void init_out_kernel(const float4* __restrict__ vattr,
                                float4* __restrict__ out, int n_pairs) {
    // Each float4 covers 2 vertex rows: {x0,y0,x1,y1} -> {0,y0,0,y1}
    int i = blockIdx.x * blockDim.x + threadIdx.x;
    if (i < n_pairs) {
        float4 v = vattr[i];
        float4 o;
        o.x = 0.0f; o.y = v.y;
        o.z = 0.0f; o.w = v.w;
        out[i] = o;
    }
}

__global__ void init_out_tail_kernel(const float* __restrict__ vattr,
                                     float* __restrict__ out,
                                     int start, int n_vertices) {
    int i = start + blockIdx.x * blockDim.x + threadIdx.x;
    if (i < n_vertices) {
        out[2 * i + 0] = 0.0f;
        out[2 * i + 1] = vattr[2 * i + 1];
    }
}

// Hot path: 16 edges/thread, branch-free. All 8 LDG.128 issued up front
// (4 int4 + 4 float4) for maximum MLP, then 16 REDs.
__global__ void __launch_bounds__(256) scatter_add_kernel(
        const int4* __restrict__ idx4,
        const float4* __restrict__ val4,
        float* __restrict__ out) {
    int t = blockIdx.x * blockDim.x + threadIdx.x;
    int g = t * 4;  // 4 quads of 4 edges = 16 edges

    int4   i0 = idx4[g + 0];
    int4   i1 = idx4[g + 1];
    int4   i2 = idx4[g + 2];
    int4   i3 = idx4[g + 3];
    float4 v0 = val4[g + 0];
    float4 v1 = val4[g + 1];
    float4 v2 = val4[g + 2];
    float4 v3 = val4[g + 3];

    red_add_f32(out + 2 * i0.x, v0.x);
    red_add_f32(out + 2 * i0.y, v0.y);
    red_add_f32(out + 2 * i0.z, v0.z);
    red_add_f32(out + 2 * i0.w, v0.w);
    red_add_f32(out + 2 * i1.x, v1.x);
    red_add_f32(out + 2 * i1.y, v1.y);
    red_add_f32(out + 2 * i1.z, v1.z);
    red_add_f32(out + 2 * i1.w, v1.w);
    red_add_f32(out + 2 * i2.x, v2.x);
    red_add_f32(out + 2 * i2.y, v2.y);
    red_add_f32(out + 2 * i2.z, v2.z);
    red_add_f32(out + 2 * i2.w, v2.w);
    red_add_f32(out + 2 * i3.x, v3.x);
    red_add_f32(out + 2 * i3.y, v3.y);
    red_add_f32(out + 2 * i3.z, v3.z);
    red_add_f32(out + 2 * i3.w, v3.w);
}

__global__ void scatter_tail_kernel(const int* __restrict__ idx,
                                    const float* __restrict__ val,
                                    float* __restrict__ out,
                                    int start, int n_edges) {
    int e = start + blockIdx.x * blockDim.x + threadIdx.x;
    if (e < n_edges)
        red_add_f32(out + 2 * idx[e], val[e]);
}

extern "C" void kernel_launch(void* const* d_in, const int* in_sizes, int n_in,
                              void* d_out, int out_size) {
    // metadata order: vertex_attr [N,2] f32, edgeij_pair [2,E] i32,
    //                 edge_attr [E,1] f32, g [1,1] f32, batch [N] i32
    const float* vattr = (const float*)d_in[0];
    const int*   eij   = (const int*)d_in[1];
    const float* eattr = (const float*)d_in[2];
    float* out = (float*)d_out;

    int n_vertices = in_sizes[0] / 2;
    int n_edges    = in_sizes[2];
    const int* src_idx = eij; // row 0 of [2, E]

    {
        int n_pairs = n_vertices / 2;  // float4 = 2 rows
        int threads = 512;
        int blocks = (n_pairs + threads - 1) / threads;
        if (blocks > 0)
            init_out_kernel<<<blocks, threads>>>(
                (const float4*)vattr, (float4*)out, n_pairs);
        if (n_vertices & 1)
            init_out_tail_kernel<<<1, 32>>>(vattr, out, n_pairs * 2, n_vertices);
    }
    {
        const int threads = 256;
        const int per_block = threads * 16;
        int full_blocks = n_edges / per_block;         // branch-free portion
        int done = full_blocks * per_block;
        if (full_blocks > 0)
            scatter_add_kernel<<<full_blocks, threads>>>(
                (const int4*)src_idx, (const float4*)eattr, out);
        int rem = n_edges - done;
        if (rem > 0) {
            int tb = 256;
            int tblocks = (rem + tb - 1) / tb;
            scatter_tail_kernel<<<tblocks, tb>>>(src_idx, eattr, out,
                                                 done, n_edges);
        }
    }
}

// round 4
// speedup vs baseline: 1.0414x; 1.0414x over previous
#include <cuda_runtime.h>

// out[i*2+0] = sum of edge_attr[e] for edges with edgeij_pair[0][e] == i
// out[i*2+1] = vertex_attr[i*2+1]

__global__ void init_out_kernel(const float4* __restrict__ vattr,
                                float4* __restrict__ out, int n_pairs) {
    // Each float4 covers 2 vertex rows: {x0,y0,x1,y1} -> {0,y0,0,y1}
    int i = blockIdx.x * blockDim.x + threadIdx.x;
    if (i < n_pairs) {
        float4 v = vattr[i];
        float4 o;
        o.x = 0.0f; o.y = v.y;
        o.z = 0.0f; o.w = v.w;
        out[i] = o;
    }
}

__global__ void init_out_tail_kernel(const float* __restrict__ vattr,
                                     float* __restrict__ out,
                                     int start, int n_vertices) {
    int i = start + blockIdx.x * blockDim.x + threadIdx.x;
    if (i < n_vertices) {
        out[2 * i + 0] = 0.0f;
        out[2 * i + 1] = vattr[2 * i + 1];
    }
}

// 2 edges per thread: one int2 + one float2 load, two REDs. Minimal
// per-thread batching -> minimal cross-CTA L1tex queue spread; the LTS
// atomic pipeline is fed by maximal thread-level parallelism instead.
__global__ void __launch_bounds__(256) scatter_add_kernel(
        const int2* __restrict__ idx2,
        const float2* __restrict__ val2,
        float* __restrict__ out, int n_pairs) {
    int t = blockIdx.x * blockDim.x + threadIdx.x;
    if (t < n_pairs) {
        int2   vi = idx2[t];
        float2 va = val2[t];
        atomicAdd(out + 2 * vi.x, va.x);
        atomicAdd(out + 2 * vi.y, va.y);
    }
}

__global__ void scatter_tail_kernel(const int* __restrict__ idx,
                                    const float* __restrict__ val,
                                    float* __restrict__ out,
                                    int start, int n_edges) {
    int e = start + blockIdx.x * blockDim.x + threadIdx.x;
    if (e < n_edges)
        atomicAdd(out + 2 * idx[e], val[e]);
}

extern "C" void kernel_launch(void* const* d_in, const int* in_sizes, int n_in,
                              void* d_out, int out_size) {
    // metadata order: vertex_attr [N,2] f32, edgeij_pair [2,E] i32,
    //                 edge_attr [E,1] f32, g [1,1] f32, batch [N] i32
    const float* vattr = (const float*)d_in[0];
    const int*   eij   = (const int*)d_in[1];
    const float* eattr = (const float*)d_in[2];
    float* out = (float*)d_out;

    int n_vertices = in_sizes[0] / 2;
    int n_edges    = in_sizes[2];
    const int* src_idx = eij; // row 0 of [2, E]

    {
        int n_pairs = n_vertices / 2;  // float4 = 2 rows
        int threads = 256;
        int blocks = (n_pairs + threads - 1) / threads;
        if (blocks > 0)
            init_out_kernel<<<blocks, threads>>>(
                (const float4*)vattr, (float4*)out, n_pairs);
        if (n_vertices & 1)
            init_out_tail_kernel<<<1, 32>>>(vattr, out, n_pairs * 2, n_vertices);
    }
    {
        const int threads = 256;
        int n_pairs = n_edges / 2;          // vectorized portion
        int blocks = (n_pairs + threads - 1) / threads;
        if (blocks > 0)
            scatter_add_kernel<<<blocks, threads>>>(
                (const int2*)src_idx, (const float2*)eattr, out, n_pairs);
        int done = n_pairs * 2;
        if (done < n_edges)
            scatter_tail_kernel<<<1, 32>>>(src_idx, eattr, out,
                                           done, n_edges);
    }
}

// round 5
// speedup vs baseline: 1.0428x; 1.0014x over previous
#include <cuda_runtime.h>

// out[i*2+0] = sum of edge_attr[e] for edges with edgeij_pair[0][e] == i
// out[i*2+1] = vertex_attr[i*2+1]

// Write-only zero of the accumulator column (out[2i]). Must precede atomics.
__global__ void zero_col0_kernel(float* __restrict__ out, int n_vertices) {
    int i = blockIdx.x * blockDim.x + threadIdx.x;
    if (i < n_vertices)
        out[2 * i] = 0.0f;
}

// 2 edges/thread scatter (empirically optimal config) + the y-column copy
// folded in: the copy is to disjoint odd words and overlaps for free under
// the atomic-pipeline-bound execution.
__global__ void __launch_bounds__(256) scatter_add_kernel(
        const int2* __restrict__ idx2,
        const float2* __restrict__ val2,
        const float* __restrict__ vattr,
        float* __restrict__ out,
        int n_pairs, int n_vertices) {
    int t = blockIdx.x * blockDim.x + threadIdx.x;

    // Folded col1 copy: first n_vertices threads (wave 1) each move one y.
    if (t < n_vertices)
        out[2 * t + 1] = vattr[2 * t + 1];

    if (t < n_pairs) {
        int2   vi = idx2[t];
        float2 va = val2[t];
        atomicAdd(out + 2 * vi.x, va.x);
        atomicAdd(out + 2 * vi.y, va.y);
    }
}

__global__ void scatter_tail_kernel(const int* __restrict__ idx,
                                    const float* __restrict__ val,
                                    float* __restrict__ out,
                                    int start, int n_edges) {
    int e = start + blockIdx.x * blockDim.x + threadIdx.x;
    if (e < n_edges)
        atomicAdd(out + 2 * idx[e], val[e]);
}

extern "C" void kernel_launch(void* const* d_in, const int* in_sizes, int n_in,
                              void* d_out, int out_size) {
    // metadata order: vertex_attr [N,2] f32, edgeij_pair [2,E] i32,
    //                 edge_attr [E,1] f32, g [1,1] f32, batch [N] i32
    const float* vattr = (const float*)d_in[0];
    const int*   eij   = (const int*)d_in[1];
    const float* eattr = (const float*)d_in[2];
    float* out = (float*)d_out;

    int n_vertices = in_sizes[0] / 2;
    int n_edges    = in_sizes[2];
    const int* src_idx = eij; // row 0 of [2, E]

    {
        int threads = 256;
        int blocks = (n_vertices + threads - 1) / threads;
        zero_col0_kernel<<<blocks, threads>>>(out, n_vertices);
    }
    {
        const int threads = 256;
        int n_pairs = n_edges / 2;          // vectorized portion
        long long need = (long long)n_pairs > (long long)n_vertices
                             ? n_pairs : n_vertices;
        int blocks = (int)((need + threads - 1) / threads);
        if (blocks > 0)
            scatter_add_kernel<<<blocks, threads>>>(
                (const int2*)src_idx, (const float2*)eattr, vattr, out,
                n_pairs, n_vertices);
        int done = n_pairs * 2;
        if (done < n_edges)
            scatter_tail_kernel<<<1, 32>>>(src_idx, eattr, out,
                                           done, n_edges);
    }
}

// round 6
// speedup vs baseline: 1.0430x; 1.0002x over previous
#include <cuda_runtime.h>

// out[i*2+0] = sum of edge_attr[e] for edges with edgeij_pair[0][e] == i
// out[i*2+1] = vertex_attr[i*2+1]

__device__ __forceinline__ float ldcs_f(const float* p) {
    float v;
    asm volatile("ld.global.cs.f32 %0, [%1];" : "=f"(v) : "l"(p));
    return v;
}

// Write-only zero of the accumulator column (out[2i]). Must precede atomics.
__global__ void zero_col0_kernel(float* __restrict__ out, int n_vertices) {
    int i = blockIdx.x * blockDim.x + threadIdx.x;
    if (i < n_vertices)
        out[2 * i] = 0.0f;
}

// Role-split fused kernel:
//   blocks [0, copy_blocks)      : copy vattr y -> out col1 (retire fast)
//   blocks [copy_blocks, total)  : 2 edges/thread atomic scatter, branch-light
// Streaming edge loads use .cs (evict-first) so the 256MB stream doesn't
// crowd the 4MB accumulator out of L2.
__global__ void __launch_bounds__(256) fused_scatter_kernel(
        const int2* __restrict__ idx2,
        const float2* __restrict__ val2,
        const float* __restrict__ vattr,
        float* __restrict__ out,
        int n_pairs, int n_vertices, int copy_blocks) {
    int b = blockIdx.x;
    if (b < copy_blocks) {
        int i = b * blockDim.x + threadIdx.x;
        if (i < n_vertices)
            out[2 * i + 1] = vattr[2 * i + 1];
        return;
    }
    int t = (b - copy_blocks) * blockDim.x + threadIdx.x;
    if (t < n_pairs) {
        const int2*   ip = idx2 + t;
        const float2* vp = val2 + t;
        int2 vi;
        asm volatile("ld.global.cs.v2.s32 {%0, %1}, [%2];"
                     : "=r"(vi.x), "=r"(vi.y) : "l"(ip));
        float2 va;
        asm volatile("ld.global.cs.v2.f32 {%0, %1}, [%2];"
                     : "=f"(va.x), "=f"(va.y) : "l"(vp));
        atomicAdd(out + 2 * vi.x, va.x);
        atomicAdd(out + 2 * vi.y, va.y);
    }
}

__global__ void scatter_tail_kernel(const int* __restrict__ idx,
                                    const float* __restrict__ val,
                                    float* __restrict__ out,
                                    int start, int n_edges) {
    int e = start + blockIdx.x * blockDim.x + threadIdx.x;
    if (e < n_edges)
        atomicAdd(out + 2 * idx[e], val[e]);
}

extern "C" void kernel_launch(void* const* d_in, const int* in_sizes, int n_in,
                              void* d_out, int out_size) {
    // metadata order: vertex_attr [N,2] f32, edgeij_pair [2,E] i32,
    //                 edge_attr [E,1] f32, g [1,1] f32, batch [N] i32
    const float* vattr = (const float*)d_in[0];
    const int*   eij   = (const int*)d_in[1];
    const float* eattr = (const float*)d_in[2];
    float* out = (float*)d_out;

    int n_vertices = in_sizes[0] / 2;
    int n_edges    = in_sizes[2];
    const int* src_idx = eij; // row 0 of [2, E]

    const int threads = 256;
    {
        int blocks = (n_vertices + threads - 1) / threads;
        zero_col0_kernel<<<blocks, threads>>>(out, n_vertices);
    }
    {
        int n_pairs = n_edges / 2;                       // vectorized portion
        int copy_blocks = (n_vertices + threads - 1) / threads;
        int edge_blocks = (n_pairs + threads - 1) / threads;
        int total = copy_blocks + edge_blocks;
        if (total > 0)
            fused_scatter_kernel<<<total, threads>>>(
                (const int2*)src_idx, (const float2*)eattr, vattr, out,
                n_pairs, n_vertices, copy_blocks);
        int done = n_pairs * 2;
        if (done < n_edges)
            scatter_tail_kernel<<<1, 32>>>(src_idx, eattr, out,
                                           done, n_edges);
    }
}